// round 1
// baseline (speedup 1.0000x reference)
#include <cuda_runtime.h>
#include <math.h>

#define P_MAX  32768
#define NCELLS 4096

// ---------------- scratch (device globals; no allocation allowed) ----------
__device__ int g_counts[NCELLS];
__device__ int g_cursor[NCELLS];
__device__ int g_cell[P_MAX];
__device__ int g_order[P_MAX];

// ---------------- cell index -----------------------------------------------
__device__ __forceinline__ int cell_of(float x0, float x1, float x2) {
    // idx = clip(int32(x / (3/16) + 8), 0, 15); int32 cast truncates toward 0 (C semantics match numpy)
    float v0 = x0 / 0.1875f + 8.0f;
    float v1 = x1 / 0.1875f + 8.0f;
    float v2 = x2 / 0.1875f + 8.0f;
    int i0 = (int)v0; i0 = min(max(i0, 0), 15);
    int i1 = (int)v1; i1 = min(max(i1, 0), 15);
    int i2 = (int)v2; i2 = min(max(i2, 0), 15);
    return (i0 * 16 + i1) * 16 + i2;
}

// ---------------- sort pipeline --------------------------------------------
__global__ void k_zero() {
    int t = blockIdx.x * blockDim.x + threadIdx.x;
    if (t < NCELLS) g_counts[t] = 0;
}

__global__ void k_count(const float* __restrict__ x, int P) {
    int p = blockIdx.x * blockDim.x + threadIdx.x;
    if (p >= P) return;
    int c = cell_of(x[3 * p], x[3 * p + 1], x[3 * p + 2]);
    g_cell[p] = c;
    atomicAdd(&g_counts[c], 1);
}

__global__ void k_scan() {
    // 1024 threads, each handles 4 cells; exclusive prefix into g_cursor
    __shared__ int s[1024];
    int t = threadIdx.x;
    int4 v = ((const int4*)g_counts)[t];
    int sum = v.x + v.y + v.z + v.w;
    s[t] = sum;
    __syncthreads();
    #pragma unroll
    for (int off = 1; off < 1024; off <<= 1) {
        int u = (t >= off) ? s[t - off] : 0;
        __syncthreads();
        s[t] += u;
        __syncthreads();
    }
    int base = s[t] - sum;  // exclusive
    g_cursor[4 * t + 0] = base;
    g_cursor[4 * t + 1] = base + v.x;
    g_cursor[4 * t + 2] = base + v.x + v.y;
    g_cursor[4 * t + 3] = base + v.x + v.y + v.z;
}

__global__ void k_scatter(int P) {
    int p = blockIdx.x * blockDim.x + threadIdx.x;
    if (p >= P) return;
    int c = g_cell[p];
    int pos = atomicAdd(&g_cursor[c], 1);
    g_order[pos] = p;
}

// ---------------- dense layer: flat float4 stream, compile-time mapping ----
template <int IN, int OUT>
__device__ __forceinline__ void dense(const float* __restrict__ wbase,
                                      const float* __restrict__ h,
                                      float* __restrict__ acc) {
    constexpr int T4 = (IN * OUT) / 4;
    static_assert((IN * OUT) % 4 == 0, "layer size must be /4");
    const float4* __restrict__ w4 = reinterpret_cast<const float4*>(wbase);
    #pragma unroll
    for (int f = 0; f < T4; f++) {
        float4 w = __ldg(w4 + f);
        acc[(4 * f + 0) % OUT] = fmaf(h[(4 * f + 0) / OUT], w.x, acc[(4 * f + 0) % OUT]);
        acc[(4 * f + 1) % OUT] = fmaf(h[(4 * f + 1) / OUT], w.y, acc[(4 * f + 1) % OUT]);
        acc[(4 * f + 2) % OUT] = fmaf(h[(4 * f + 2) / OUT], w.z, acc[(4 * f + 2) % OUT]);
        acc[(4 * f + 3) % OUT] = fmaf(h[(4 * f + 3) / OUT], w.w, acc[(4 * f + 3) % OUT]);
    }
}

// ---------------- main MLP kernel ------------------------------------------
__global__ __launch_bounds__(128) void k_mlp(
    const float* __restrict__ x,   const float* __restrict__ d,
    const float* __restrict__ l1w, const float* __restrict__ l1b,
    const float* __restrict__ l2w, const float* __restrict__ l2b,
    const float* __restrict__ l3w, const float* __restrict__ l3b,
    const float* __restrict__ l4w, const float* __restrict__ l4b,
    const float* __restrict__ l5w, const float* __restrict__ l5b,
    float* __restrict__ out, int P)
{
    int t = blockIdx.x * blockDim.x + threadIdx.x;
    if (t >= P) return;
    int p = g_order[t];       // sorted by cell -> adjacent lanes share weights
    int c = g_cell[p];

    float x0 = x[3 * p], x1 = x[3 * p + 1], x2 = x[3 * p + 2];
    float d0 = d[3 * p], d1 = d[3 * p + 1], d2 = d[3 * p + 2];
    bool mask = (fabsf(x0) < 1.5f) && (fabsf(x1) < 1.5f) && (fabsf(x2) < 1.5f);

    // positional encoding of x: [x, sin(2^0 x), cos(2^0 x), ..., j<10] = 63 feats
    // double-angle recurrence: one sinf/cosf per component
    float emb[63];
    {
        float xs[3] = {x0, x1, x2};
        #pragma unroll
        for (int q = 0; q < 3; q++) {
            float xv = xs[q];
            emb[q] = xv;
            float s = sinf(xv), cc = cosf(xv);
            #pragma unroll
            for (int j = 0; j < 10; j++) {
                emb[3 + 6 * j + q] = s;
                emb[6 + 6 * j + q] = cc;
                float ns = 2.0f * s * cc;
                float nc = 1.0f - 2.0f * s * s;
                s = ns; cc = nc;
            }
        }
    }

    float acc[33];

    // ---- layer 1: 63 -> 32, relu ----
    {
        const float4* b4 = (const float4*)(l1b + c * 32);
        #pragma unroll
        for (int q = 0; q < 8; q++) {
            float4 b = __ldg(b4 + q);
            acc[4 * q + 0] = b.x; acc[4 * q + 1] = b.y;
            acc[4 * q + 2] = b.z; acc[4 * q + 3] = b.w;
        }
        dense<63, 32>(l1w + (size_t)c * (63 * 32), emb, acc);
    }
    float h1[32];
    #pragma unroll
    for (int q = 0; q < 32; q++) h1[q] = fmaxf(acc[q], 0.0f);

    // ---- layer 2: 32 -> 33, relu; last col = density ----
    {
        const float* b = l2b + c * 33;   // not 16B aligned per cell: scalar loads
        #pragma unroll
        for (int q = 0; q < 33; q++) acc[q] = __ldg(b + q);
        dense<32, 33>(l2w + (size_t)c * (32 * 33), h1, acc);
    }
    float density = fmaxf(acc[32], 0.0f);
    float h2[32];
    #pragma unroll
    for (int q = 0; q < 32; q++) h2[q] = fmaxf(acc[q], 0.0f);

    // ---- layer 3: 32 -> 32, NO activation; result goes to hcat[0..31] ----
    float hcat[59];
    {
        const float4* b4 = (const float4*)(l3b + c * 32);
        #pragma unroll
        for (int q = 0; q < 8; q++) {
            float4 b = __ldg(b4 + q);
            acc[4 * q + 0] = b.x; acc[4 * q + 1] = b.y;
            acc[4 * q + 2] = b.z; acc[4 * q + 3] = b.w;
        }
        dense<32, 32>(l3w + (size_t)c * (32 * 32), h2, acc);
        #pragma unroll
        for (int q = 0; q < 32; q++) hcat[q] = acc[q];
    }

    // dir encoding into hcat[32..58]: [d, sin/cos j<4] = 27 feats
    {
        float ds[3] = {d0, d1, d2};
        #pragma unroll
        for (int q = 0; q < 3; q++) {
            float dv = ds[q];
            hcat[32 + q] = dv;
            float s = sinf(dv), cc = cosf(dv);
            #pragma unroll
            for (int j = 0; j < 4; j++) {
                hcat[35 + 6 * j + q] = s;
                hcat[38 + 6 * j + q] = cc;
                float ns = 2.0f * s * cc;
                float nc = 1.0f - 2.0f * s * s;
                s = ns; cc = nc;
            }
        }
    }

    // ---- layer 4: 59 -> 32, relu ----
    {
        const float4* b4 = (const float4*)(l4b + c * 32);
        #pragma unroll
        for (int q = 0; q < 8; q++) {
            float4 b = __ldg(b4 + q);
            acc[4 * q + 0] = b.x; acc[4 * q + 1] = b.y;
            acc[4 * q + 2] = b.z; acc[4 * q + 3] = b.w;
        }
        dense<59, 32>(l4w + (size_t)c * (59 * 32), hcat, acc);
    }
    float h4[32];
    #pragma unroll
    for (int q = 0; q < 32; q++) h4[q] = fmaxf(acc[q], 0.0f);

    // ---- layer 5: 32 -> 3, sigmoid ----
    float a5[3];
    {
        const float* b = l5b + c * 3;
        a5[0] = __ldg(b + 0); a5[1] = __ldg(b + 1); a5[2] = __ldg(b + 2);
        dense<32, 3>(l5w + (size_t)c * (32 * 3), h4, a5);
    }
    float c0 = 1.0f / (1.0f + expf(-a5[0]));
    float c1 = 1.0f / (1.0f + expf(-a5[1]));
    float c2 = 1.0f / (1.0f + expf(-a5[2]));

    // ---- masked write: out = [color (P,3) flattened, sigma (P)] ----
    out[3 * p + 0] = mask ? c0 : 0.0f;
    out[3 * p + 1] = mask ? c1 : 0.0f;
    out[3 * p + 2] = mask ? c2 : 0.0f;
    out[3 * P + p] = mask ? density : 0.0f;
}

// ---------------- launch ----------------------------------------------------
extern "C" void kernel_launch(void* const* d_in, const int* in_sizes, int n_in,
                              void* d_out, int out_size) {
    const float* x   = (const float*)d_in[0];
    const float* d   = (const float*)d_in[1];
    const float* l1w = (const float*)d_in[2];
    const float* l1b = (const float*)d_in[3];
    const float* l2w = (const float*)d_in[4];
    const float* l2b = (const float*)d_in[5];
    const float* l3w = (const float*)d_in[6];
    const float* l3b = (const float*)d_in[7];
    const float* l4w = (const float*)d_in[8];
    const float* l4b = (const float*)d_in[9];
    const float* l5w = (const float*)d_in[10];
    const float* l5b = (const float*)d_in[11];
    float* out = (float*)d_out;

    int P = in_sizes[0] / 3;
    if (P > P_MAX) P = P_MAX;

    k_zero<<<(NCELLS + 255) / 256, 256>>>();
    k_count<<<(P + 255) / 256, 256>>>(x, P);
    k_scan<<<1, 1024>>>();
    k_scatter<<<(P + 255) / 256, 256>>>(P);
    k_mlp<<<(P + 127) / 128, 128>>>(x, d, l1w, l1b, l2w, l2b, l3w, l3b,
                                    l4w, l4b, l5w, l5b, out, P);
}